// round 1
// baseline (speedup 1.0000x reference)
#include <cuda_runtime.h>
#include <cstdint>

// Problem constants
#define SEQ_LEN  120
#define BATCH    2048
#define INPUT    6
#define HID      64
#define GATES    256          // 4*HID, torch gate order i,f,g,o
#define LAYERS   4
#define TLEN     120
#define NB       16           // batch elements per CTA
#define NCTA     (BATCH / NB) // 128
#define NTHR     256

// ---------------- transposed weight scratch (device globals; no allocs) ----
#define S_W0   (GATES * INPUT)          // 1536
#define S_WIH  ((LAYERS - 1) * GATES * HID) // 49152
#define S_WHH  (LAYERS * GATES * HID)   // 65536

__device__ float g_eW0t[INPUT * GATES];          // [k][j]
__device__ float g_eWiht[(LAYERS - 1) * HID * GATES];
__device__ float g_eWhht[LAYERS * HID * GATES];
__device__ float g_dW0t[INPUT * GATES];
__device__ float g_dWiht[(LAYERS - 1) * HID * GATES];
__device__ float g_dWhht[LAYERS * HID * GATES];

__global__ void lstm36206574305735_transpose(
    const float* __restrict__ eW0, const float* __restrict__ eWih,
    const float* __restrict__ eWhh, const float* __restrict__ dW0,
    const float* __restrict__ dWih, const float* __restrict__ dWhh)
{
    const int tot = 2 * (S_W0 + S_WIH + S_WHH);
    for (int idx = blockIdx.x * blockDim.x + threadIdx.x; idx < tot;
         idx += gridDim.x * blockDim.x) {
        int r = idx;
        if (r < S_W0) {                       // enc Wih0 [256][6] -> [6][256]
            int j = r / INPUT, k = r % INPUT;
            g_eW0t[k * GATES + j] = eW0[r];
            continue;
        }
        r -= S_W0;
        if (r < S_W0) {                       // dec Wih0
            int j = r / INPUT, k = r % INPUT;
            g_dW0t[k * GATES + j] = dW0[r];
            continue;
        }
        r -= S_W0;
        if (r < S_WIH) {                      // enc Wih [3][256][64] -> [3][64][256]
            int l = r / (GATES * HID), rr = r % (GATES * HID);
            int j = rr / HID, k = rr % HID;
            g_eWiht[l * HID * GATES + k * GATES + j] = eWih[r];
            continue;
        }
        r -= S_WIH;
        if (r < S_WIH) {                      // dec Wih
            int l = r / (GATES * HID), rr = r % (GATES * HID);
            int j = rr / HID, k = rr % HID;
            g_dWiht[l * HID * GATES + k * GATES + j] = dWih[r];
            continue;
        }
        r -= S_WIH;
        if (r < S_WHH) {                      // enc Whh [4][256][64] -> [4][64][256]
            int l = r / (GATES * HID), rr = r % (GATES * HID);
            int j = rr / HID, k = rr % HID;
            g_eWhht[l * HID * GATES + k * GATES + j] = eWhh[r];
            continue;
        }
        r -= S_WHH;
        {                                     // dec Whh
            int l = r / (GATES * HID), rr = r % (GATES * HID);
            int j = rr / HID, k = rr % HID;
            g_dWhht[l * HID * GATES + k * GATES + j] = dWhh[r];
        }
    }
}

// ---------------- fast activations ----------------------------------------
__device__ __forceinline__ float fsig(float x) {
    return __fdividef(1.0f, 1.0f + __expf(-x));
}
__device__ __forceinline__ float ftanh_(float x) {
    return 2.0f * fsig(2.0f * x) - 1.0f;
}

// gemv phase: acc[b] += sum_k Wt[k*GATES + j] * hs[k*NB + b]
template <int K>
__device__ __forceinline__ void gemv_acc(float acc[NB],
                                         const float* __restrict__ Wt,
                                         const float* __restrict__ hs,
                                         int j)
{
#pragma unroll 8
    for (int k = 0; k < K; k++) {
        float w = Wt[k * GATES + j];
        const float4* hp = reinterpret_cast<const float4*>(hs + k * NB);
#pragma unroll
        for (int q = 0; q < 4; q++) {
            float4 hv = hp[q];
            acc[4 * q + 0] += w * hv.x;
            acc[4 * q + 1] += w * hv.y;
            acc[4 * q + 2] += w * hv.z;
            acc[4 * q + 3] += w * hv.w;
        }
    }
}

// one time step through the full stack
__device__ __forceinline__ void lstm_stack_step(
    const float* __restrict__ W0t, const float* __restrict__ Wiht,
    const float* __restrict__ Whht, const float* __restrict__ bias4,
    float* __restrict__ h_s,   // [LAYERS][HID][NB]
    float* __restrict__ c_s,   // [LAYERS][HID][NB]
    float (* __restrict__ g_s)[NB + 1],  // padded gates [GATES][17]
    const float* __restrict__ in_s,      // [INPUT][NB]
    int j)
{
    for (int l = 0; l < LAYERS; l++) {
        float acc[NB];
#pragma unroll
        for (int b = 0; b < NB; b++) acc[b] = bias4[l];

        if (l == 0) {
            gemv_acc<INPUT>(acc, W0t, in_s, j);
        } else {
            gemv_acc<HID>(acc, Wiht + (size_t)(l - 1) * HID * GATES,
                          h_s + (size_t)(l - 1) * HID * NB, j);
        }
        gemv_acc<HID>(acc, Whht + (size_t)l * HID * GATES,
                      h_s + (size_t)l * HID * NB, j);

#pragma unroll
        for (int b = 0; b < NB; b++) g_s[j][b] = acc[b];
        __syncthreads();

        // cell update: 64*16 = 1024 items, 4 per thread
        float* hl = h_s + (size_t)l * HID * NB;
        float* cl = c_s + (size_t)l * HID * NB;
#pragma unroll
        for (int r = 0; r < (HID * NB) / NTHR; r++) {
            int idx = j + r * NTHR;
            int hh = idx >> 4;
            int b  = idx & (NB - 1);
            float gi = g_s[hh][b];
            float gf = g_s[HID + hh][b];
            float gg = g_s[2 * HID + hh][b];
            float go = g_s[3 * HID + hh][b];
            float cold = cl[hh * NB + b];
            float cn = fsig(gf) * cold + fsig(gi) * ftanh_(gg);
            cl[hh * NB + b] = cn;
            hl[hh * NB + b] = fsig(go) * ftanh_(cn);
        }
        __syncthreads();
    }
}

// smem layout (floats)
#define OFF_H   0
#define OFF_C   (OFF_H + LAYERS * HID * NB)       // 4096
#define OFF_G   (OFF_C + LAYERS * HID * NB)       // 8192
#define OFF_IN  (OFF_G + GATES * (NB + 1))        // 8192+4352 = 12544
#define OFF_LW  (OFF_IN + INPUT * NB)             // 12640
#define OFF_LB  (OFF_LW + HID * INPUT)            // 13024
#define SMEM_FLOATS (OFF_LB + INPUT + 2)
#define SMEM_BYTES  (SMEM_FLOATS * 4)

__global__ void __launch_bounds__(NTHR, 1)
lstm36206574305735_main(const float* __restrict__ x,
                        const float* __restrict__ eB,
                        const float* __restrict__ dB,
                        const float* __restrict__ linW,
                        const float* __restrict__ linB,
                        float* __restrict__ out)
{
    extern __shared__ float smem[];
    float* h_s = smem + OFF_H;
    float* c_s = smem + OFF_C;
    float (*g_s)[NB + 1] = reinterpret_cast<float(*)[NB + 1]>(smem + OFF_G);
    float* in_s = smem + OFF_IN;   // [INPUT][NB]
    float* lw_s = smem + OFF_LW;   // [HID][INPUT] (transposed lin_W)
    float* lb_s = smem + OFF_LB;

    const int j  = threadIdx.x;
    const int b0 = blockIdx.x * NB;

    // zero state
    for (int i = j; i < 2 * LAYERS * HID * NB; i += NTHR) smem[i] = 0.0f;
    // stage lin weights transposed: lw_s[hh*INPUT + i] = linW[i*HID + hh]
    for (int i = j; i < HID * INPUT; i += NTHR) {
        int hh = i / INPUT, ii = i % INPUT;
        lw_s[hh * INPUT + ii] = linW[ii * HID + hh];
    }
    if (j < INPUT) lb_s[j] = linB[j];

    // per-thread biases
    float be[LAYERS], bd[LAYERS];
#pragma unroll
    for (int l = 0; l < LAYERS; l++) {
        be[l] = eB[l * GATES + j];
        bd[l] = dB[l * GATES + j];
    }
    __syncthreads();

    // -------- encoder --------
    for (int t = 0; t < SEQ_LEN; t++) {
        if (j < INPUT * NB) {
            int b = j / INPUT, i = j % INPUT;
            in_s[i * NB + b] = x[((size_t)t * BATCH + b0 + b) * INPUT + i];
        }
        __syncthreads();
        lstm_stack_step(g_eW0t, g_eWiht, g_eWhht, be, h_s, c_s, g_s, in_s, j);
    }
    // in_s now holds x[SEQ_LEN-1] == decoder seed

    // -------- decoder --------
    for (int t = 0; t < TLEN; t++) {
        lstm_stack_step(g_dW0t, g_dWiht, g_dWhht, bd, h_s, c_s, g_s, in_s, j);

        // out[b][i] = lin_b[i] + sum_h lin_W[i][h] * h_top[h][b]
        if (j < INPUT * NB) {
            int b = j / INPUT, i = j % INPUT;
            const float* htop = h_s + (size_t)(LAYERS - 1) * HID * NB;
            float v = lb_s[i];
#pragma unroll 8
            for (int hh = 0; hh < HID; hh++)
                v += lw_s[hh * INPUT + i] * htop[hh * NB + b];
            out[((size_t)t * BATCH + b0 + b) * INPUT + i] = v;
            in_s[i * NB + b] = v;   // feedback
        }
        __syncthreads();
    }
}

extern "C" void kernel_launch(void* const* d_in, const int* in_sizes, int n_in,
                              void* d_out, int out_size)
{
    const float* x    = (const float*)d_in[0];
    const float* eW0  = (const float*)d_in[1];
    const float* eWih = (const float*)d_in[2];
    const float* eWhh = (const float*)d_in[3];
    const float* eB   = (const float*)d_in[4];
    const float* dW0  = (const float*)d_in[5];
    const float* dWih = (const float*)d_in[6];
    const float* dWhh = (const float*)d_in[7];
    const float* dB   = (const float*)d_in[8];
    const float* linW = (const float*)d_in[9];
    const float* linB = (const float*)d_in[10];
    float* out = (float*)d_out;

    lstm36206574305735_transpose<<<908, 256>>>(eW0, eWih, eWhh, dW0, dWih, dWhh);

    cudaFuncSetAttribute(lstm36206574305735_main,
                         cudaFuncAttributeMaxDynamicSharedMemorySize, SMEM_BYTES);
    lstm36206574305735_main<<<NCTA, NTHR, SMEM_BYTES>>>(x, eB, dB, linW, linB, out);
}